// round 1
// baseline (speedup 1.0000x reference)
#include <cuda_runtime.h>
#include <cstdint>

// ---------------- model constants ----------------
#define BSZ      512
#define NCH      129
#define NT       250
#define DINNER   256
#define DSTATE   16
#define DCONV    4
#define HEADDIM  64
#define NHEADS   4
#define CONVDIM  (DINNER + 2*DSTATE)          // 288
#define DPROJ    (2*DINNER + 2*DSTATE + NHEADS) // 548
#define EPSV     1e-5f

// ---------------- device scratch (no cudaMalloc allowed) ----------------
__device__ float g_W[DPROJ * NCH];            // 548 x 129 fused projection
__device__ float g_bias[DPROJ];
__device__ float g_v[DINNER];                 // out_proj^T @ head_w
__device__ float g_zxbcdt[(size_t)BSZ * NT * DPROJ];   // 512*250*548 floats (~281 MB)

// ---------------- packed f32x2 helpers ----------------
typedef unsigned long long ull;
__device__ __forceinline__ ull dup2(float v) {
    ull r; asm("mov.b64 %0, {%1, %1};" : "=l"(r) : "f"(v)); return r;
}
__device__ __forceinline__ ull ffma2(ull a, ull b, ull c) {
    ull d; asm("fma.rn.f32x2 %0, %1, %2, %3;" : "=l"(d) : "l"(a), "l"(b), "l"(c)); return d;
}
__device__ __forceinline__ float2 unpk2(ull v) {
    float2 f; asm("mov.b64 {%0, %1}, %2;" : "=f"(f.x), "=f"(f.y) : "l"(v)); return f;
}

// =====================================================================
// Kernel 1: precompute fused weights
//   W[j,c]   = sum_d in_proj_w[j,d] * mixer_w[d,c]
//   bias[j]  = sum_d in_proj_w[j,d] * mixer_b[d]
//   v[i]     = sum_d out_proj_w[d,i] * head_w[d]
// =====================================================================
__global__ void prep_kernel(const float* __restrict__ in_proj_w,
                            const float* __restrict__ mixer_w,
                            const float* __restrict__ mixer_b,
                            const float* __restrict__ out_proj_w,
                            const float* __restrict__ head_w) {
    int idx = blockIdx.x * blockDim.x + threadIdx.x;
    const int NW = DPROJ * NCH;
    if (idx < NW) {
        int j = idx / NCH, c = idx - j * NCH;
        float acc = 0.f;
        #pragma unroll 4
        for (int d = 0; d < 128; d++)
            acc = fmaf(in_proj_w[j * 128 + d], mixer_w[d * NCH + c], acc);
        g_W[idx] = acc;
    } else if (idx < NW + DPROJ) {
        int j = idx - NW;
        float acc = 0.f;
        for (int d = 0; d < 128; d++)
            acc = fmaf(in_proj_w[j * 128 + d], mixer_b[d], acc);
        g_bias[j] = acc;
    } else if (idx < NW + DPROJ + DINNER) {
        int i = idx - NW - DPROJ;
        float acc = 0.f;
        for (int d = 0; d < 128; d++)
            acc = fmaf(out_proj_w[d * DINNER + i], head_w[d], acc);
        g_v[i] = acc;
    }
}

// =====================================================================
// Kernel 2: fused projection GEMM
//   zxbcdt[b,t,j] = sum_c W[j,c] * x[b,c,t] + bias[j]
//   64x64 tile per block, 256 threads, thread computes 4j x 4t via f32x2 FMA.
// =====================================================================
#define GPAD 68   // shared row pitch (floats), multiple of 4
__global__ void gemm_kernel(const float* __restrict__ x) {
    extern __shared__ float sm[];
    float* xs = sm;                  // [129][GPAD]  x tile (c, t)
    float* wt = sm + NCH * GPAD;     // [129][GPAD]  W tile transposed (c, j)

    const int tid = threadIdx.x;
    const int j0 = blockIdx.x * 64;
    const int t0 = blockIdx.y * 64;
    const int b  = blockIdx.z;

    const float* xb = x + (size_t)b * (NCH * NT);
    for (int i = tid; i < NCH * 64; i += 256) {
        int c = i >> 6, tt = i & 63;
        int t = t0 + tt;
        xs[c * GPAD + tt] = (t < NT) ? xb[c * NT + t] : 0.f;
    }
    for (int i = tid; i < 64 * NCH; i += 256) {
        int jj = i / NCH, c = i - jj * NCH;
        int j = j0 + jj;
        wt[c * GPAD + jj] = (j < DPROJ) ? g_W[j * NCH + c] : 0.f;
    }
    __syncthreads();

    const int jg = tid & 15;   // adjacent lanes -> adjacent j (coalesced store)
    const int tg = tid >> 4;

    ull acc[4][2];
    #pragma unroll
    for (int r = 0; r < 4; r++) { acc[r][0] = 0ULL; acc[r][1] = 0ULL; }

    const float* xr = xs + tg * 4;
    const float* wr = wt + jg * 4;

    #pragma unroll 3
    for (int c = 0; c < NCH; c++) {
        ull x01 = *(const ull*)(xr);
        ull x23 = *(const ull*)(xr + 2);
        float4 wv = *(const float4*)(wr);
        ull w;
        w = dup2(wv.x); acc[0][0] = ffma2(w, x01, acc[0][0]); acc[0][1] = ffma2(w, x23, acc[0][1]);
        w = dup2(wv.y); acc[1][0] = ffma2(w, x01, acc[1][0]); acc[1][1] = ffma2(w, x23, acc[1][1]);
        w = dup2(wv.z); acc[2][0] = ffma2(w, x01, acc[2][0]); acc[2][1] = ffma2(w, x23, acc[2][1]);
        w = dup2(wv.w); acc[3][0] = ffma2(w, x01, acc[3][0]); acc[3][1] = ffma2(w, x23, acc[3][1]);
        xr += GPAD; wr += GPAD;
    }

    int j = j0 + jg * 4;
    if (j + 3 < DPROJ) {            // 548 % 4 == 0, so tiles are all-or-nothing
        float4 bs = *(const float4*)(g_bias + j);
        float r[4][4];
        #pragma unroll
        for (int jr = 0; jr < 4; jr++) {
            float2 lo = unpk2(acc[jr][0]);
            float2 hi = unpk2(acc[jr][1]);
            r[jr][0] = lo.x; r[jr][1] = lo.y; r[jr][2] = hi.x; r[jr][3] = hi.y;
        }
        #pragma unroll
        for (int tr = 0; tr < 4; tr++) {
            int t = t0 + tg * 4 + tr;
            if (t < NT) {
                float4 o;
                o.x = r[0][tr] + bs.x; o.y = r[1][tr] + bs.y;
                o.z = r[2][tr] + bs.z; o.w = r[3][tr] + bs.w;
                *(float4*)(g_zxbcdt + ((size_t)b * NT + t) * DPROJ + j) = o;
            }
        }
    }
}

// =====================================================================
// Kernel 3: fused conv1d + SiLU + softplus(dt) + SSM scan + gating +
//           RMSNorm + (out_proj∘pool∘head collapsed to v-dot).
//   One block per batch element. 288 threads (256 scan channels + 32 B/C).
// =====================================================================
__global__ void __launch_bounds__(288, 3)
scan_kernel(const float* __restrict__ conv_w, const float* __restrict__ conv_b,
            const float* __restrict__ dt_bias, const float* __restrict__ A_log,
            const float* __restrict__ Dp, const float* __restrict__ norm_w,
            const float* __restrict__ head_b, float* __restrict__ out) {
    const int b = blockIdx.x;
    const int tid = threadIdx.x;           // 0..287
    const int lane = tid & 31, wid = tid >> 5;
    const int h = tid >> 6;                // head (valid for tid<256)

    __shared__ float sB[DSTATE], sC[DSTATE], sdt[NHEADS], sdA[NHEADS];
    __shared__ float sred[9];
    __shared__ float smean;

    // conv params for this channel
    float w0 = conv_w[tid * 4 + 0], w1 = conv_w[tid * 4 + 1];
    float w2 = conv_w[tid * 4 + 2], w3 = conv_w[tid * 4 + 3];
    float cb = conv_b[tid];
    float xm3 = 0.f, xm2 = 0.f, xm1 = 0.f;  // causal history (zero padded)

    float nwvv = 0.f, Dh = 0.f;
    if (tid < DINNER) { nwvv = norm_w[tid] * g_v[tid]; Dh = Dp[h]; }
    float dtb = 0.f, Aneg = 0.f;
    if (tid < NHEADS) { dtb = dt_bias[tid]; Aneg = -expf(A_log[tid]); }

    float s[DSTATE];
    #pragma unroll
    for (int n = 0; n < DSTATE; n++) s[n] = 0.f;
    float acc = 0.f;

    const float* row = g_zxbcdt + (size_t)b * NT * DPROJ;

    for (int t = 0; t < NT; t++) {
        const float* r = row + (size_t)t * DPROJ;

        float raw  = r[DINNER + tid];                      // xBC pre-conv, ch=tid
        float zval = (tid < DINNER) ? r[tid] : 0.f;

        // depthwise conv (register ring) + SiLU
        float cv = fmaf(w3, raw, fmaf(w2, xm1, fmaf(w1, xm2, fmaf(w0, xm3, cb))));
        xm3 = xm2; xm2 = xm1; xm1 = raw;
        float cs = cv / (1.f + expf(-cv));                 // silu

        if (tid >= DINNER) {
            if (tid < DINNER + DSTATE) sB[tid - DINNER] = cs;
            else                       sC[tid - DINNER - DSTATE] = cs;
        }
        if (tid < NHEADS) {
            float rv = r[DPROJ - NHEADS + tid] + dtb;
            float dtv = (rv > 20.f) ? rv : log1pf(expf(rv)); // softplus
            sdt[tid] = dtv;
            sdA[tid] = expf(dtv * Aneg);
        }
        __syncthreads();

        float g = 0.f;
        if (tid < DINNER) {
            float dAv = sdA[h];
            float dx  = sdt[h] * cs;
            float y = 0.f;
            #pragma unroll
            for (int n = 0; n < DSTATE; n++) {
                s[n] = fmaf(s[n], dAv, dx * sB[n]);
                y = fmaf(s[n], sC[n], y);
            }
            y = fmaf(Dh, cs, y);
            g = y * (zval / (1.f + expf(-zval)));          // gate: y * silu(z)
        }

        // RMSNorm: block-reduce g^2 over the 256 scan channels
        float ss = g * g;
        #pragma unroll
        for (int o = 16; o > 0; o >>= 1) ss += __shfl_xor_sync(0xffffffffu, ss, o);
        if (lane == 0) sred[wid] = ss;
        __syncthreads();
        if (tid == 0) {
            float tot = 0.f;
            #pragma unroll
            for (int w = 0; w < 9; w++) tot += sred[w];
            smean = tot * (1.f / 256.f);
        }
        __syncthreads();
        if (tid < DINNER) {
            float rms = rsqrtf(smean + EPSV);
            acc = fmaf(g * rms, nwvv, acc);    // yn dot v, accumulated over t
        }
        __syncthreads();   // protect sB/sC/sdt/sred/smean for next step
    }

    // final reduce of acc across block
    #pragma unroll
    for (int o = 16; o > 0; o >>= 1) acc += __shfl_xor_sync(0xffffffffu, acc, o);
    if (lane == 0) sred[wid] = acc;
    __syncthreads();
    if (tid == 0) {
        float tot = 0.f;
        #pragma unroll
        for (int w = 0; w < 9; w++) tot += sred[w];
        out[b] = tot * (1.f / (float)NT) + head_b[0];
    }
}

// =====================================================================
// launch
// =====================================================================
extern "C" void kernel_launch(void* const* d_in, const int* in_sizes, int n_in,
                              void* d_out, int out_size) {
    const float* x          = (const float*)d_in[0];
    const float* mixer_w    = (const float*)d_in[1];
    const float* mixer_b    = (const float*)d_in[2];
    const float* in_proj_w  = (const float*)d_in[3];
    const float* conv_w     = (const float*)d_in[4];
    const float* conv_b     = (const float*)d_in[5];
    const float* dt_bias    = (const float*)d_in[6];
    const float* A_log      = (const float*)d_in[7];
    const float* Dvec       = (const float*)d_in[8];
    const float* norm_w     = (const float*)d_in[9];
    const float* out_proj_w = (const float*)d_in[10];
    const float* head_w     = (const float*)d_in[11];
    const float* head_b     = (const float*)d_in[12];
    float* out = (float*)d_out;

    // 1) fused weights
    {
        int total = DPROJ * NCH + DPROJ + DINNER;
        prep_kernel<<<(total + 255) / 256, 256>>>(in_proj_w, mixer_w, mixer_b,
                                                  out_proj_w, head_w);
    }

    // 2) projection GEMM (dynamic smem > 48KB)
    {
        int smem = 2 * NCH * GPAD * (int)sizeof(float);   // 70176 B
        cudaFuncSetAttribute(gemm_kernel,
                             cudaFuncAttributeMaxDynamicSharedMemorySize, smem);
        dim3 grid((DPROJ + 63) / 64, (NT + 63) / 64, BSZ);  // (9, 4, 512)
        gemm_kernel<<<grid, 256, smem>>>(x);
    }

    // 3) fused scan -> final output
    scan_kernel<<<BSZ, 288>>>(conv_w, conv_b, dt_bias, A_log, Dvec,
                              norm_w, head_b, out);
}

// round 3
// speedup vs baseline: 1.4482x; 1.4482x over previous
#include <cuda_runtime.h>
#include <cuda_bf16.h>
#include <cstdint>

// ---------------- model constants ----------------
#define BSZ      512
#define NCH      129
#define NT       250
#define DINNER   256
#define DSTATE   16
#define NHEADS   4
#define CONVDIM  288
#define DPROJ    548
#define EPSV     1e-5f

// GEMM tiling
#define TM   128          // t rows per CTA
#define TN   144          // j cols per CTA (548 -> 4 chunks of 144, pad 576)
#define TK   144          // K padded (real K = 129), 9 k-steps of 16
#define NJC  4
#define NKK  9
#define APITCH 152        // bf16 pitch: 76-word row stride -> conflict-free frags
#define BPITCH 152
#define SPITCH 148        // fp32 staging pitch

// ---------------- device scratch (no cudaMalloc allowed) ----------------
__device__ float g_W[DPROJ * NCH];
__device__ float g_bias[DPROJ];
__device__ float g_v[DINNER];
__device__ float g_zxbcdt[(size_t)BSZ * NT * DPROJ];
// W pre-split bf16 hi/lo: [sel][jc][n(144)][k(144)] row-major
__device__ __align__(16) __nv_bfloat16 g_Wsplit[2 * NJC * TN * TK];

// ---------------- smem layout (bytes) ----------------
#define SM_AHI   0
#define SM_ALO   (TM * APITCH * 2)                    // 38912
#define SM_BHI   (2 * TM * APITCH * 2)                // 77824
#define SM_BLO   (SM_BHI + TN * BPITCH * 2)           // +43776
#define SMEM_SZ  (SM_BLO + TN * BPITCH * 2)           // 165376

// =====================================================================
// mma.sync m16n8k16 bf16 (base sm_103 PTX — NO tcgen05)
// =====================================================================
__device__ __forceinline__ void mma16816(float* d, const uint32_t* a, const uint32_t* b) {
    asm volatile(
        "mma.sync.aligned.m16n8k16.row.col.f32.bf16.bf16.f32 "
        "{%0,%1,%2,%3}, {%4,%5,%6,%7}, {%8,%9}, {%0,%1,%2,%3};"
        : "+f"(d[0]), "+f"(d[1]), "+f"(d[2]), "+f"(d[3])
        : "r"(a[0]), "r"(a[1]), "r"(a[2]), "r"(a[3]), "r"(b[0]), "r"(b[1]));
}

// =====================================================================
// prep1: fused weights
//   W[j,c] = in_proj_w[j,:] . mixer_w[:,c]; bias; v = out_proj^T.head_w
// =====================================================================
__global__ void prep1_kernel(const float* __restrict__ in_proj_w,
                             const float* __restrict__ mixer_w,
                             const float* __restrict__ mixer_b,
                             const float* __restrict__ out_proj_w,
                             const float* __restrict__ head_w) {
    int idx = blockIdx.x * blockDim.x + threadIdx.x;
    const int NW = DPROJ * NCH;
    if (idx < NW) {
        int j = idx / NCH, c = idx - j * NCH;
        float acc = 0.f;
        #pragma unroll 4
        for (int d = 0; d < 128; d++)
            acc = fmaf(in_proj_w[j * 128 + d], mixer_w[d * NCH + c], acc);
        g_W[idx] = acc;
    } else if (idx < NW + DPROJ) {
        int j = idx - NW;
        float acc = 0.f;
        for (int d = 0; d < 128; d++)
            acc = fmaf(in_proj_w[j * 128 + d], mixer_b[d], acc);
        g_bias[j] = acc;
    } else if (idx < NW + DPROJ + DINNER) {
        int i = idx - NW - DPROJ;
        float acc = 0.f;
        for (int d = 0; d < 128; d++)
            acc = fmaf(out_proj_w[d * DINNER + i], head_w[d], acc);
        g_v[i] = acc;
    }
}

// =====================================================================
// prep2: split W -> bf16 hi/lo padded chunk tiles [sel][jc][n][k]
// =====================================================================
__global__ void prep2_kernel() {
    int idx = blockIdx.x * blockDim.x + threadIdx.x;
    const int CH = TN * TK;
    if (idx >= 2 * NJC * CH) return;
    int s  = idx / (NJC * CH);
    int jc = (idx / CH) % NJC;
    int w  = idx % CH;
    int n  = w / TK;
    int k  = w % TK;
    int j  = jc * TN + n;
    float val = (j < DPROJ && k < NCH) ? g_W[j * NCH + k] : 0.f;
    __nv_bfloat16 hi = __float2bfloat16(val);
    __nv_bfloat16 o = hi;
    if (s == 1) o = __float2bfloat16(val - __bfloat162float(hi));
    g_Wsplit[idx] = o;
}

// =====================================================================
// gemm_mma: 3-pass bf16 split GEMM on HMMA (mma.sync)
//   zxbcdt[b,t,j] = sum_c x[b,c,t] * W[j,c] + bias[j]
//   grid (2 t-tiles, 4 j-chunks, 512 b), 256 thr, 8 warps (4m x 2n)
// =====================================================================
__global__ void __launch_bounds__(256, 1) gemm_mma(const float* __restrict__ x) {
    extern __shared__ __align__(16) unsigned char sm[];
    const int tid = threadIdx.x;
    const int wid = tid >> 5, lane = tid & 31;
    const int gid = lane >> 2, tig = lane & 3;
    const int wm = wid & 3, wn = wid >> 2;
    const int tt = blockIdx.x, jc = blockIdx.y, b = blockIdx.z;
    const int t0 = tt * TM;

    // ---- B tiles: 16B copies of pre-split W chunk (row-major 144 -> pitch 152)
    {
        const unsigned char* srcH = (const unsigned char*)(g_Wsplit + (size_t)(0 * NJC + jc) * (TN * TK));
        const unsigned char* srcL = (const unsigned char*)(g_Wsplit + (size_t)(1 * NJC + jc) * (TN * TK));
        // per row: 144 bf16 = 288 B = 18 uint4
        for (int i = tid; i < TN * 18; i += 256) {
            int n = i / 18, kq = i % 18;
            *(uint4*)(sm + SM_BHI + n * (BPITCH * 2) + kq * 16) =
                *(const uint4*)(srcH + n * (TK * 2) + kq * 16);
            *(uint4*)(sm + SM_BLO + n * (BPITCH * 2) + kq * 16) =
                *(const uint4*)(srcL + n * (TK * 2) + kq * 16);
        }
    }

    // ---- A tile: x fp32 -> bf16 hi/lo, A[t][c] pitch 152
    {
        const float* xb = x + (size_t)b * (NCH * NT);
        for (int i = tid; i < TK * TM; i += 256) {     // c-major, t fast: coalesced
            int c = i >> 7, m = i & (TM - 1);
            int t = t0 + m;
            float v = (c < NCH && t < NT) ? xb[(size_t)c * NT + t] : 0.f;
            __nv_bfloat16 h = __float2bfloat16(v);
            __nv_bfloat16 l = __float2bfloat16(v - __bfloat162float(h));
            uint32_t off = (uint32_t)m * (APITCH * 2) + (uint32_t)c * 2;
            *(__nv_bfloat16*)(sm + SM_AHI + off) = h;
            *(__nv_bfloat16*)(sm + SM_ALO + off) = l;
        }
    }
    __syncthreads();

    // ---- main loop: 3 passes (AhiBhi, AhiBlo, AloBhi) x 9 k-steps ----
    float acc[2][9][4];
    #pragma unroll
    for (int mi = 0; mi < 2; mi++)
        #pragma unroll
        for (int ni = 0; ni < 9; ni++)
            #pragma unroll
            for (int q = 0; q < 4; q++) acc[mi][ni][q] = 0.f;

    #pragma unroll
    for (int p = 0; p < 3; p++) {
        const unsigned char* Ab = sm + (p == 2 ? SM_ALO : SM_AHI);
        const unsigned char* Bb = sm + (p == 1 ? SM_BLO : SM_BHI);
        #pragma unroll
        for (int kk = 0; kk < NKK; kk++) {
            const int k0 = kk * 16;
            uint32_t af[2][4];
            #pragma unroll
            for (int mi = 0; mi < 2; mi++) {
                int r = wm * 32 + mi * 16 + gid;
                const unsigned char* Ar  = Ab + ((uint32_t)r * (APITCH * 2) + (k0 + 2 * tig) * 2);
                const unsigned char* Ar8 = Ar + 8 * (APITCH * 2);
                af[mi][0] = *(const uint32_t*)Ar;
                af[mi][1] = *(const uint32_t*)Ar8;
                af[mi][2] = *(const uint32_t*)(Ar + 16);
                af[mi][3] = *(const uint32_t*)(Ar8 + 16);
            }
            #pragma unroll
            for (int ni = 0; ni < 9; ni++) {
                int n = wn * 72 + ni * 8 + gid;
                const unsigned char* Bn = Bb + ((uint32_t)n * (BPITCH * 2) + (k0 + 2 * tig) * 2);
                uint32_t bf[2];
                bf[0] = *(const uint32_t*)Bn;
                bf[1] = *(const uint32_t*)(Bn + 16);
                mma16816(acc[0][ni], af[0], bf);
                mma16816(acc[1][ni], af[1], bf);
            }
        }
    }

    // ---- stage accumulators to smem (reuse A region), coalesced store ----
    __syncthreads();
    float* stage = (float*)(sm);            // 128 x SPITCH fp32 = 75776 B
    #pragma unroll
    for (int mi = 0; mi < 2; mi++) {
        #pragma unroll
        for (int ni = 0; ni < 9; ni++) {
            int r = wm * 32 + mi * 16 + gid;
            int c = wn * 72 + ni * 8 + 2 * tig;
            float* s0 = stage + r * SPITCH + c;
            float* s8 = s0 + 8 * SPITCH;
            s0[0] = acc[mi][ni][0]; s0[1] = acc[mi][ni][1];
            s8[0] = acc[mi][ni][2]; s8[1] = acc[mi][ni][3];
        }
    }
    __syncthreads();

    // ---- global store: +bias, float4, coalesced ----
    for (int i = tid; i < TM * (TN / 4); i += 256) {
        int row = i / (TN / 4), q = i % (TN / 4);
        int t = t0 + row;
        int j = jc * TN + 4 * q;
        if (t < NT && j + 3 < DPROJ) {
            const float* sp = stage + row * SPITCH + 4 * q;
            float4 bs = *(const float4*)(g_bias + j);
            float4 o;
            o.x = sp[0] + bs.x; o.y = sp[1] + bs.y;
            o.z = sp[2] + bs.z; o.w = sp[3] + bs.w;
            *(float4*)(g_zxbcdt + ((size_t)b * NT + t) * DPROJ + j) = o;
        }
    }
}

// =====================================================================
// scan: fused conv1d+SiLU+softplus+SSM+gate+RMSNorm+v-dot (pipelined)
// =====================================================================
__global__ void __launch_bounds__(288, 4)
scan_kernel(const float* __restrict__ conv_w, const float* __restrict__ conv_b,
            const float* __restrict__ dt_bias, const float* __restrict__ A_log,
            const float* __restrict__ Dp, const float* __restrict__ norm_w,
            const float* __restrict__ head_b, float* __restrict__ out) {
    const int b = blockIdx.x;
    const int tid = threadIdx.x;
    const int lane = tid & 31, wid = tid >> 5;
    const int h = tid >> 6;

    __shared__ float sB[2][DSTATE], sC[2][DSTATE], sdt[2][NHEADS], sdA[2][NHEADS];
    __shared__ float sred[2][9];

    float w0 = conv_w[tid * 4 + 0], w1 = conv_w[tid * 4 + 1];
    float w2 = conv_w[tid * 4 + 2], w3 = conv_w[tid * 4 + 3];
    float cb = conv_b[tid];
    float xm3 = 0.f, xm2 = 0.f, xm1 = 0.f;

    float nwvv = 0.f, Dh = 0.f;
    if (tid < DINNER) { nwvv = norm_w[tid] * g_v[tid]; Dh = Dp[h]; }
    float dtb = 0.f, Aneg = 0.f;
    if (tid < NHEADS) { dtb = dt_bias[tid]; Aneg = -expf(A_log[tid]); }

    float s[DSTATE];
    #pragma unroll
    for (int n = 0; n < DSTATE; n++) s[n] = 0.f;
    float acc = 0.f;

    const float* row = g_zxbcdt + (size_t)b * NT * DPROJ;

    float raw  = row[DINNER + tid];
    float zval = (tid < DINNER) ? row[tid] : 0.f;
    float dtr  = (tid < NHEADS) ? row[DPROJ - NHEADS + tid] : 0.f;

    for (int t = 0; t < NT; t++) {
        const int buf = t & 1;

        float cv = fmaf(w3, raw, fmaf(w2, xm1, fmaf(w1, xm2, fmaf(w0, xm3, cb))));
        xm3 = xm2; xm2 = xm1; xm1 = raw;
        float cs = cv / (1.f + expf(-cv));

        if (tid >= DINNER) {
            if (tid < DINNER + DSTATE) sB[buf][tid - DINNER] = cs;
            else                       sC[buf][tid - DINNER - DSTATE] = cs;
        }
        if (tid < NHEADS) {
            float rv = dtr + dtb;
            float dtv = (rv > 20.f) ? rv : log1pf(expf(rv));
            sdt[buf][tid] = dtv;
            sdA[buf][tid] = expf(dtv * Aneg);
        }

        float nraw = 0.f, nzval = 0.f, ndtr = 0.f;
        if (t + 1 < NT) {
            const float* rn = row + (size_t)(t + 1) * DPROJ;
            nraw = rn[DINNER + tid];
            if (tid < DINNER) nzval = rn[tid];
            if (tid < NHEADS) ndtr = rn[DPROJ - NHEADS + tid];
        }
        __syncthreads();

        float g = 0.f;
        if (tid < DINNER) {
            float dAv = sdA[buf][h];
            float dx  = sdt[buf][h] * cs;
            float y = 0.f;
            #pragma unroll
            for (int n = 0; n < DSTATE; n++) {
                s[n] = fmaf(s[n], dAv, dx * sB[buf][n]);
                y = fmaf(s[n], sC[buf][n], y);
            }
            y = fmaf(Dh, cs, y);
            g = y * (zval / (1.f + expf(-zval)));
        }

        float ss = g * g;
        #pragma unroll
        for (int o = 16; o > 0; o >>= 1) ss += __shfl_xor_sync(0xffffffffu, ss, o);
        if (lane == 0) sred[buf][wid] = ss;
        __syncthreads();

        float tot = 0.f;
        #pragma unroll
        for (int w = 0; w < 9; w++) tot += sred[buf][w];
        if (tid < DINNER)
            acc = fmaf(g * rsqrtf(tot * (1.f / 256.f) + EPSV), nwvv, acc);

        raw = nraw; zval = nzval; dtr = ndtr;
    }

    __syncthreads();
    #pragma unroll
    for (int o = 16; o > 0; o >>= 1) acc += __shfl_xor_sync(0xffffffffu, acc, o);
    if (lane == 0) sred[0][wid] = acc;
    __syncthreads();
    if (tid == 0) {
        float tot = 0.f;
        #pragma unroll
        for (int w = 0; w < 9; w++) tot += sred[0][w];
        out[b] = tot * (1.f / (float)NT) + head_b[0];
    }
}

// =====================================================================
// launch
// =====================================================================
extern "C" void kernel_launch(void* const* d_in, const int* in_sizes, int n_in,
                              void* d_out, int out_size) {
    const float* x          = (const float*)d_in[0];
    const float* mixer_w    = (const float*)d_in[1];
    const float* mixer_b    = (const float*)d_in[2];
    const float* in_proj_w  = (const float*)d_in[3];
    const float* conv_w     = (const float*)d_in[4];
    const float* conv_b     = (const float*)d_in[5];
    const float* dt_bias    = (const float*)d_in[6];
    const float* A_log      = (const float*)d_in[7];
    const float* Dvec       = (const float*)d_in[8];
    const float* norm_w     = (const float*)d_in[9];
    const float* out_proj_w = (const float*)d_in[10];
    const float* head_w     = (const float*)d_in[11];
    const float* head_b     = (const float*)d_in[12];
    float* out = (float*)d_out;

    {
        int total = DPROJ * NCH + DPROJ + DINNER;
        prep1_kernel<<<(total + 255) / 256, 256>>>(in_proj_w, mixer_w, mixer_b,
                                                   out_proj_w, head_w);
    }
    {
        int total = 2 * NJC * TN * TK;
        prep2_kernel<<<(total + 255) / 256, 256>>>();
    }
    {
        cudaFuncSetAttribute(gemm_mma,
                             cudaFuncAttributeMaxDynamicSharedMemorySize, SMEM_SZ);
        dim3 grid(2, NJC, BSZ);
        gemm_mma<<<grid, 256, SMEM_SZ>>>(x);
    }
    scan_kernel<<<BSZ, 288>>>(conv_w, conv_b, dt_bias, A_log, Dvec,
                              norm_w, head_b, out);
}

// round 4
// speedup vs baseline: 1.5640x; 1.0799x over previous
#include <cuda_runtime.h>
#include <cuda_bf16.h>
#include <cstdint>

// ---------------- model constants ----------------
#define BSZ      512
#define NCH      129
#define NT       250
#define DINNER   256
#define DSTATE   16
#define NHEADS   4
#define CONVDIM  288
#define DPROJ    548
#define EPSV     1e-5f

// GEMM tiling: K split as 128 (MMA) + 1 (rank-1 epilogue fixup)
#define TM     128        // t rows per CTA
#define TN     72         // j cols per CTA (548 -> 8 chunks of 72, pad 576)
#define TK     128        // MMA K (channel 128 handled in epilogue)
#define NJC    8
#define NKK    8          // 8 k-steps of 16
#define PITCH  136        // bf16 smem pitch (272 B): conflict-free ldmatrix
#define PITCHB 272
#define SPITCH 76         // fp32 staging pitch

// ---------------- device scratch ----------------
__device__ float g_W[DPROJ * NCH];
__device__ float g_bias[DPROJ];
__device__ float g_v[DINNER];
__device__ float g_zxbcdt[(size_t)BSZ * NT * DPROJ];
// W pre-split bf16 hi/lo for k=0..127: [sel][jc][n(72)][k(128)]
__device__ __align__(16) __nv_bfloat16 g_Wsplit2[2 * NJC * TN * TK];
__device__ float g_Wcol[576];    // W[j][128], zero-padded to 576
__device__ float g_biasP[576];   // bias, zero-padded

// ---------------- smem layout (bytes) ----------------
#define SM_AHI   0                      // 128*272 = 34816
#define SM_ALO   34816
#define SM_BHI   69632                  // 72*272 = 19584
#define SM_BLO   89216
#define SM_X128  108800                 // 128 fp32
#define SM_W128  109312                 // 72 fp32
#define SM_BIAS  109600                 // 72 fp32
#define SMEM_SZ  109888

// ---------------- packed f32x2 helpers (compiled OK at sm_103 in R1) ----
typedef unsigned long long ull;
__device__ __forceinline__ ull dup2(float v) {
    ull r; asm("mov.b64 %0, {%1, %1};" : "=l"(r) : "f"(v)); return r;
}
__device__ __forceinline__ ull ffma2(ull a, ull b, ull c) {
    ull d; asm("fma.rn.f32x2 %0, %1, %2, %3;" : "=l"(d) : "l"(a), "l"(b), "l"(c)); return d;
}
__device__ __forceinline__ ull fmul2(ull a, ull b) {
    ull d; asm("mul.rn.f32x2 %0, %1, %2;" : "=l"(d) : "l"(a), "l"(b)); return d;
}
__device__ __forceinline__ float2 unpk2(ull v) {
    float2 f; asm("mov.b64 {%0, %1}, %2;" : "=f"(f.x), "=f"(f.y) : "l"(v)); return f;
}

// ---------------- mma / ldmatrix (base sm_103 PTX) ----------------
__device__ __forceinline__ void mma16816(float* d, const uint32_t* a, const uint32_t* b) {
    asm volatile(
        "mma.sync.aligned.m16n8k16.row.col.f32.bf16.bf16.f32 "
        "{%0,%1,%2,%3}, {%4,%5,%6,%7}, {%8,%9}, {%0,%1,%2,%3};"
        : "+f"(d[0]), "+f"(d[1]), "+f"(d[2]), "+f"(d[3])
        : "r"(a[0]), "r"(a[1]), "r"(a[2]), "r"(a[3]), "r"(b[0]), "r"(b[1]));
}
__device__ __forceinline__ void ldsm4(uint32_t* r, uint32_t addr) {
    asm volatile("ldmatrix.sync.aligned.m8n8.x4.shared.b16 {%0,%1,%2,%3}, [%4];"
        : "=r"(r[0]), "=r"(r[1]), "=r"(r[2]), "=r"(r[3]) : "r"(addr));
}
__device__ __forceinline__ void ldsm2(uint32_t* r, uint32_t addr) {
    asm volatile("ldmatrix.sync.aligned.m8n8.x2.shared.b16 {%0,%1}, [%2];"
        : "=r"(r[0]), "=r"(r[1]) : "r"(addr));
}
__device__ __forceinline__ uint32_t smem_u32(const void* p) {
    uint32_t a;
    asm("{ .reg .u64 t; cvta.to.shared.u64 t, %1; cvt.u32.u64 %0, t; }" : "=r"(a) : "l"(p));
    return a;
}

// =====================================================================
// prep1: fused weights W = in_proj . mixer, bias, v = out_proj^T . head
// =====================================================================
__global__ void prep1_kernel(const float* __restrict__ in_proj_w,
                             const float* __restrict__ mixer_w,
                             const float* __restrict__ mixer_b,
                             const float* __restrict__ out_proj_w,
                             const float* __restrict__ head_w) {
    int idx = blockIdx.x * blockDim.x + threadIdx.x;
    const int NW = DPROJ * NCH;
    if (idx < NW) {
        int j = idx / NCH, c = idx - j * NCH;
        float acc = 0.f;
        #pragma unroll 4
        for (int d = 0; d < 128; d++)
            acc = fmaf(in_proj_w[j * 128 + d], mixer_w[d * NCH + c], acc);
        g_W[idx] = acc;
    } else if (idx < NW + DPROJ) {
        int j = idx - NW;
        float acc = 0.f;
        for (int d = 0; d < 128; d++)
            acc = fmaf(in_proj_w[j * 128 + d], mixer_b[d], acc);
        g_bias[j] = acc;
    } else if (idx < NW + DPROJ + DINNER) {
        int i = idx - NW - DPROJ;
        float acc = 0.f;
        for (int d = 0; d < 128; d++)
            acc = fmaf(out_proj_w[d * DINNER + i], head_w[d], acc);
        g_v[i] = acc;
    }
}

// =====================================================================
// prep2: split W (k<128) -> bf16 hi/lo chunk tiles; pad Wcol/bias
// =====================================================================
__global__ void prep2_kernel() {
    int idx = blockIdx.x * blockDim.x + threadIdx.x;
    const int NSPLIT = 2 * NJC * TN * TK;    // 147456
    if (idx < NSPLIT) {
        int k = idx & 127;
        int t = idx >> 7;
        int n = t % TN; t /= TN;
        int jc = t % NJC;
        int s = t / NJC;
        int j = jc * TN + n;
        float val = (j < DPROJ) ? g_W[j * NCH + k] : 0.f;
        __nv_bfloat16 hi = __float2bfloat16(val);
        __nv_bfloat16 o = hi;
        if (s == 1) o = __float2bfloat16(val - __bfloat162float(hi));
        g_Wsplit2[idx] = o;
    } else if (idx < NSPLIT + 576) {
        int j = idx - NSPLIT;
        g_Wcol[j] = (j < DPROJ) ? g_W[j * NCH + 128] : 0.f;
    } else if (idx < NSPLIT + 1152) {
        int j = idx - NSPLIT - 576;
        g_biasP[j] = (j < DPROJ) ? g_bias[j] : 0.f;
    }
}

// =====================================================================
// gemm_mma: 3-pass bf16 split GEMM, ldmatrix frags, 2 CTAs/SM
//   grid (2 tt, 8 jc, 512 b), 256 thr, 8 warps each 16(m) x 72(n)
// =====================================================================
__global__ void __launch_bounds__(256, 2) gemm_mma(const float* __restrict__ x) {
    extern __shared__ __align__(16) unsigned char sm[];
    const uint32_t sbase = smem_u32(sm);
    const int tid = threadIdx.x;
    const int wid = tid >> 5, lane = tid & 31;
    const int gid = lane >> 2, tig = lane & 3;
    const int tt = blockIdx.x, jc = blockIdx.y, b = blockIdx.z;
    const int t0 = tt * TM;

    // ---- B tiles: 16B copies of pre-split chunk (256B/row -> pitch 272)
    {
        const unsigned char* srcH = (const unsigned char*)(g_Wsplit2 + (size_t)(0 * NJC + jc) * (TN * TK));
        const unsigned char* srcL = (const unsigned char*)(g_Wsplit2 + (size_t)(1 * NJC + jc) * (TN * TK));
        for (int i = tid; i < TN * 16; i += 256) {
            int n = i >> 4, q = i & 15;
            *(uint4*)(sm + SM_BHI + n * PITCHB + q * 16) = *(const uint4*)(srcH + n * 256 + q * 16);
            *(uint4*)(sm + SM_BLO + n * PITCHB + q * 16) = *(const uint4*)(srcL + n * 256 + q * 16);
        }
    }
    // ---- A tile: x fp32 -> bf16 hi/lo pairs (c pairs -> 32-bit STS)
    {
        const float* xb = x + (size_t)b * (NCH * NT);
        for (int i = tid; i < 64 * TM; i += 256) {      // 8192, 32 iters
            int cp = i >> 7, m = i & (TM - 1);
            int t = t0 + m;
            int c0 = 2 * cp;
            float v0 = (t < NT) ? xb[(size_t)c0 * NT + t] : 0.f;
            float v1 = (t < NT) ? xb[(size_t)(c0 + 1) * NT + t] : 0.f;
            __nv_bfloat16 h0 = __float2bfloat16(v0), h1 = __float2bfloat16(v1);
            __nv_bfloat16 l0 = __float2bfloat16(v0 - __bfloat162float(h0));
            __nv_bfloat16 l1 = __float2bfloat16(v1 - __bfloat162float(h1));
            uint32_t off = (uint32_t)m * PITCHB + (uint32_t)cp * 4;
            *(__nv_bfloat162*)(sm + SM_AHI + off) = __nv_bfloat162{h0, h1};
            *(__nv_bfloat162*)(sm + SM_ALO + off) = __nv_bfloat162{l0, l1};
        }
    }
    // ---- epilogue constants
    if (tid < 128) {
        int t = t0 + tid;
        const float* xb = x + (size_t)b * (NCH * NT);
        *(float*)(sm + SM_X128 + tid * 4) = (t < NT) ? xb[(size_t)128 * NT + t] : 0.f;
        if (tid < TN) {
            *(float*)(sm + SM_W128 + tid * 4) = g_Wcol[jc * TN + tid];
            *(float*)(sm + SM_BIAS + tid * 4) = g_biasP[jc * TN + tid];
        }
    }
    __syncthreads();

    // ---- mainloop: 3 passes x 8 k-steps, ldmatrix frags ----
    float acc[9][4];
    #pragma unroll
    for (int ni = 0; ni < 9; ni++)
        #pragma unroll
        for (int q = 0; q < 4; q++) acc[ni][q] = 0.f;

    const uint32_t aOff = (uint32_t)(wid * 16 + (lane & 15)) * PITCHB + (uint32_t)(lane >> 4) * 16;
    const uint32_t bOff = (uint32_t)(lane & 15) * PITCHB + (uint32_t)(lane >> 4) * 16;
    const uint32_t b2Off = (uint32_t)(64 + (lane & 7)) * PITCHB + (uint32_t)((lane >> 3) & 1) * 16;

    #pragma unroll
    for (int p = 0; p < 3; p++) {
        const uint32_t Ab = sbase + (p == 2 ? SM_ALO : SM_AHI) + aOff;
        const uint32_t Bb = sbase + (p == 1 ? SM_BLO : SM_BHI) + bOff;
        const uint32_t Bb2 = sbase + (p == 1 ? SM_BLO : SM_BHI) + b2Off;
        #pragma unroll
        for (int kk = 0; kk < NKK; kk++) {
            uint32_t a[4];
            ldsm4(a, Ab + kk * 32);
            #pragma unroll
            for (int q = 0; q < 4; q++) {
                uint32_t bb[4];
                ldsm4(bb, Bb + (uint32_t)(q * 16) * PITCHB + kk * 32);
                uint32_t f0[2] = { bb[0], bb[2] };
                uint32_t f1[2] = { bb[1], bb[3] };
                mma16816(acc[2 * q], a, f0);
                mma16816(acc[2 * q + 1], a, f1);
            }
            uint32_t b2[2];
            ldsm2(b2, Bb2 + kk * 32);
            mma16816(acc[8], a, b2);
        }
    }

    // ---- stage accumulators to smem (reuse A region) ----
    __syncthreads();
    float* stage = (float*)sm;              // 128 x 76 fp32 = 38912 B
    {
        int r = wid * 16 + gid;
        #pragma unroll
        for (int ni = 0; ni < 9; ni++) {
            int c = ni * 8 + 2 * tig;
            *(float2*)(stage + r * SPITCH + c) = make_float2(acc[ni][0], acc[ni][1]);
            *(float2*)(stage + (r + 8) * SPITCH + c) = make_float2(acc[ni][2], acc[ni][3]);
        }
    }
    __syncthreads();

    // ---- global store: + x[.,128,t]*W[.,128] + bias, coalesced float4 ----
    const float* xs128 = (const float*)(sm + SM_X128);
    const float* sW = (const float*)(sm + SM_W128);
    const float* sBs = (const float*)(sm + SM_BIAS);
    for (int i = tid; i < TM * (TN / 4); i += 256) {    // 128*18
        int row = i / (TN / 4), q = i % (TN / 4);
        int t = t0 + row;
        int j = jc * TN + 4 * q;
        if (t < NT && j + 3 < DPROJ) {
            const float* sp = stage + row * SPITCH + 4 * q;
            float xk = xs128[row];
            float4 o;
            o.x = fmaf(xk, sW[4 * q + 0], sp[0] + sBs[4 * q + 0]);
            o.y = fmaf(xk, sW[4 * q + 1], sp[1] + sBs[4 * q + 1]);
            o.z = fmaf(xk, sW[4 * q + 2], sp[2] + sBs[4 * q + 2]);
            o.w = fmaf(xk, sW[4 * q + 3], sp[3] + sBs[4 * q + 3]);
            *(float4*)(g_zxbcdt + ((size_t)b * NT + t) * DPROJ + j) = o;
        }
    }
}

// =====================================================================
// scan: fused conv1d+SiLU+softplus+SSM+gate+RMSNorm+v-dot
//   packed f32x2 state update + MUFU transcendentals
// =====================================================================
__global__ void __launch_bounds__(288, 4)
scan_kernel(const float* __restrict__ conv_w, const float* __restrict__ conv_b,
            const float* __restrict__ dt_bias, const float* __restrict__ A_log,
            const float* __restrict__ Dp, const float* __restrict__ norm_w,
            const float* __restrict__ head_b, float* __restrict__ out) {
    const int b = blockIdx.x;
    const int tid = threadIdx.x;
    const int lane = tid & 31, wid = tid >> 5;
    const int h = tid >> 6;

    __shared__ __align__(16) float sB[2][DSTATE];
    __shared__ __align__(16) float sC[2][DSTATE];
    __shared__ float sdt[2][NHEADS], sdA[2][NHEADS];
    __shared__ float sred[2][9];

    float w0 = conv_w[tid * 4 + 0], w1 = conv_w[tid * 4 + 1];
    float w2 = conv_w[tid * 4 + 2], w3 = conv_w[tid * 4 + 3];
    float cb = conv_b[tid];
    float xm3 = 0.f, xm2 = 0.f, xm1 = 0.f;

    float nwvv = 0.f, Dh = 0.f;
    if (tid < DINNER) { nwvv = norm_w[tid] * g_v[tid]; Dh = Dp[h]; }
    float dtb = 0.f, Aneg = 0.f;
    if (tid < NHEADS) { dtb = dt_bias[tid]; Aneg = -expf(A_log[tid]); }

    ull s2[8];
    #pragma unroll
    for (int n = 0; n < 8; n++) s2[n] = 0ULL;
    float acc = 0.f;

    const float* row = g_zxbcdt + (size_t)b * NT * DPROJ;

    float raw  = row[DINNER + tid];
    float zval = (tid < DINNER) ? row[tid] : 0.f;
    float dtr  = (tid < NHEADS) ? row[DPROJ - NHEADS + tid] : 0.f;

    for (int t = 0; t < NT; t++) {
        const int buf = t & 1;

        // conv + fast silu
        float cv = fmaf(w3, raw, fmaf(w2, xm1, fmaf(w1, xm2, fmaf(w0, xm3, cb))));
        xm3 = xm2; xm2 = xm1; xm1 = raw;
        float cs = __fdividef(cv, 1.f + __expf(-cv));

        if (tid >= DINNER) {
            if (tid < DINNER + DSTATE) sB[buf][tid - DINNER] = cs;
            else                       sC[buf][tid - DINNER - DSTATE] = cs;
        }
        if (tid < NHEADS) {
            float rv = dtr + dtb;
            float dtv = (rv > 15.f) ? rv : __logf(1.f + __expf(rv));
            sdt[buf][tid] = dtv;
            sdA[buf][tid] = __expf(dtv * Aneg);
        }

        // prefetch t+1
        float nraw = 0.f, nzval = 0.f, ndtr = 0.f;
        if (t + 1 < NT) {
            const float* rn = row + (size_t)(t + 1) * DPROJ;
            nraw = rn[DINNER + tid];
            if (tid < DINNER) nzval = rn[tid];
            if (tid < NHEADS) ndtr = rn[DPROJ - NHEADS + tid];
        }
        __syncthreads();

        float g = 0.f;
        if (tid < DINNER) {
            ull dA2 = dup2(sdA[buf][h]);
            ull dx2 = dup2(sdt[buf][h] * cs);
            ull y2 = 0ULL;
            #pragma unroll
            for (int np = 0; np < 8; np++) {
                ull Bp = *(const ull*)(&sB[buf][2 * np]);
                ull Cp = *(const ull*)(&sC[buf][2 * np]);
                s2[np] = ffma2(s2[np], dA2, fmul2(dx2, Bp));
                y2 = ffma2(s2[np], Cp, y2);
            }
            float2 yy = unpk2(y2);
            float y = fmaf(Dh, cs, yy.x + yy.y);
            g = y * __fdividef(zval, 1.f + __expf(-zval));
        }

        float ss = g * g;
        #pragma unroll
        for (int o = 16; o > 0; o >>= 1) ss += __shfl_xor_sync(0xffffffffu, ss, o);
        if (lane == 0) sred[buf][wid] = ss;
        __syncthreads();

        float tot = 0.f;
        #pragma unroll
        for (int w = 0; w < 9; w++) tot += sred[buf][w];
        if (tid < DINNER)
            acc = fmaf(g * rsqrtf(tot * (1.f / 256.f) + EPSV), nwvv, acc);

        raw = nraw; zval = nzval; dtr = ndtr;
    }

    __syncthreads();
    #pragma unroll
    for (int o = 16; o > 0; o >>= 1) acc += __shfl_xor_sync(0xffffffffu, acc, o);
    if (lane == 0) sred[0][wid] = acc;
    __syncthreads();
    if (tid == 0) {
        float tot = 0.f;
        #pragma unroll
        for (int w = 0; w < 9; w++) tot += sred[0][w];
        out[b] = tot * (1.f / (float)NT) + head_b[0];
    }
}

// =====================================================================
// launch
// =====================================================================
extern "C" void kernel_launch(void* const* d_in, const int* in_sizes, int n_in,
                              void* d_out, int out_size) {
    const float* x          = (const float*)d_in[0];
    const float* mixer_w    = (const float*)d_in[1];
    const float* mixer_b    = (const float*)d_in[2];
    const float* in_proj_w  = (const float*)d_in[3];
    const float* conv_w     = (const float*)d_in[4];
    const float* conv_b     = (const float*)d_in[5];
    const float* dt_bias    = (const float*)d_in[6];
    const float* A_log      = (const float*)d_in[7];
    const float* Dvec       = (const float*)d_in[8];
    const float* norm_w     = (const float*)d_in[9];
    const float* out_proj_w = (const float*)d_in[10];
    const float* head_w     = (const float*)d_in[11];
    const float* head_b     = (const float*)d_in[12];
    float* out = (float*)d_out;

    {
        int total = DPROJ * NCH + DPROJ + DINNER;
        prep1_kernel<<<(total + 255) / 256, 256>>>(in_proj_w, mixer_w, mixer_b,
                                                   out_proj_w, head_w);
    }
    {
        int total = 2 * NJC * TN * TK + 1152;
        prep2_kernel<<<(total + 255) / 256, 256>>>();
    }
    {
        cudaFuncSetAttribute(gemm_mma,
                             cudaFuncAttributeMaxDynamicSharedMemorySize, SMEM_SZ);
        dim3 grid(2, NJC, BSZ);
        gemm_mma<<<grid, 256, SMEM_SZ>>>(x);
    }
    scan_kernel<<<BSZ, 288>>>(conv_w, conv_b, dt_bias, A_log, Dvec,
                              norm_w, head_b, out);
}

// round 5
// speedup vs baseline: 2.5205x; 1.6116x over previous
#include <cuda_runtime.h>
#include <cuda_fp16.h>
#include <cstdint>

// ---------------- model constants ----------------
#define BSZ      512
#define NCH      129
#define NT       250
#define DINNER   256
#define DSTATE   16
#define NHEADS   4
#define CONVDIM  288
#define DPROJ    548
#define EPSV     1e-5f

// GEMM tiling: K = 128 (MMA) + 1 (rank-1 epilogue fixup)
#define TM     128
#define TN     72         // 548 -> 8 chunks of 72 (pad 576)
#define TK     128
#define NJC    8
#define NKK    8
#define PITCHB 272        // smem row pitch bytes: conflict-free ldmatrix
#define SPITCH 76         // fp32 staging pitch

// ---------------- device scratch ----------------
__device__ float g_W[DPROJ * NCH];
__device__ float g_bias[DPROJ];
__device__ float g_v[DINNER];
__device__ float g_zxbcdt[(size_t)BSZ * NT * DPROJ];
__device__ __align__(16) __half g_Wh[NJC * TN * TK];   // W fp16, k<128
__device__ float g_Wcol[576];    // W[j][128] zero-padded
__device__ float g_biasP[576];

// ---------------- smem layout (bytes) ----------------
#define SM_AHI   0                      // 128*272 = 34816
#define SM_ALO   34816
#define SM_BH    69632                  // 72*272 = 19584
#define SM_X128  89216                  // 128 fp32
#define SM_W128  89728                  // 72 fp32
#define SM_BIAS  90016                  // 72 fp32
#define SMEM_SZ  90304

// ---------------- packed f32x2 helpers ----------------
typedef unsigned long long ull;
__device__ __forceinline__ ull dup2(float v) {
    ull r; asm("mov.b64 %0, {%1, %1};" : "=l"(r) : "f"(v)); return r;
}
__device__ __forceinline__ ull pack2(float lo, float hi) {
    ull r; asm("mov.b64 %0, {%1, %2};" : "=l"(r) : "f"(lo), "f"(hi)); return r;
}
__device__ __forceinline__ ull ffma2(ull a, ull b, ull c) {
    ull d; asm("fma.rn.f32x2 %0, %1, %2, %3;" : "=l"(d) : "l"(a), "l"(b), "l"(c)); return d;
}
__device__ __forceinline__ ull fmul2(ull a, ull b) {
    ull d; asm("mul.rn.f32x2 %0, %1, %2;" : "=l"(d) : "l"(a), "l"(b)); return d;
}
__device__ __forceinline__ float2 unpk2(ull v) {
    float2 f; asm("mov.b64 {%0, %1}, %2;" : "=f"(f.x), "=f"(f.y) : "l"(v)); return f;
}

// ---------------- mma / ldmatrix (base sm_103 PTX) ----------------
__device__ __forceinline__ void mma16816(float* d, const uint32_t* a, const uint32_t* b) {
    asm volatile(
        "mma.sync.aligned.m16n8k16.row.col.f32.f16.f16.f32 "
        "{%0,%1,%2,%3}, {%4,%5,%6,%7}, {%8,%9}, {%0,%1,%2,%3};"
        : "+f"(d[0]), "+f"(d[1]), "+f"(d[2]), "+f"(d[3])
        : "r"(a[0]), "r"(a[1]), "r"(a[2]), "r"(a[3]), "r"(b[0]), "r"(b[1]));
}
__device__ __forceinline__ void ldsm4(uint32_t* r, uint32_t addr) {
    asm volatile("ldmatrix.sync.aligned.m8n8.x4.shared.b16 {%0,%1,%2,%3}, [%4];"
        : "=r"(r[0]), "=r"(r[1]), "=r"(r[2]), "=r"(r[3]) : "r"(addr));
}
__device__ __forceinline__ void ldsm2(uint32_t* r, uint32_t addr) {
    asm volatile("ldmatrix.sync.aligned.m8n8.x2.shared.b16 {%0,%1}, [%2];"
        : "=r"(r[0]), "=r"(r[1]) : "r"(addr));
}
__device__ __forceinline__ uint32_t smem_u32(const void* p) {
    uint32_t a;
    asm("{ .reg .u64 t; cvta.to.shared.u64 t, %1; cvt.u32.u64 %0, t; }" : "=r"(a) : "l"(p));
    return a;
}

// =====================================================================
// prep1: fused weights (4 partial accumulators to break FMA chain)
// =====================================================================
__global__ void prep1_kernel(const float* __restrict__ in_proj_w,
                             const float* __restrict__ mixer_w,
                             const float* __restrict__ mixer_b,
                             const float* __restrict__ out_proj_w,
                             const float* __restrict__ head_w) {
    int idx = blockIdx.x * blockDim.x + threadIdx.x;
    const int NW = DPROJ * NCH;
    if (idx < NW) {
        int j = idx / NCH, c = idx - j * NCH;
        float a0 = 0.f, a1 = 0.f, a2 = 0.f, a3 = 0.f;
        #pragma unroll 8
        for (int d = 0; d < 128; d += 4) {
            a0 = fmaf(in_proj_w[j * 128 + d + 0], mixer_w[(d + 0) * NCH + c], a0);
            a1 = fmaf(in_proj_w[j * 128 + d + 1], mixer_w[(d + 1) * NCH + c], a1);
            a2 = fmaf(in_proj_w[j * 128 + d + 2], mixer_w[(d + 2) * NCH + c], a2);
            a3 = fmaf(in_proj_w[j * 128 + d + 3], mixer_w[(d + 3) * NCH + c], a3);
        }
        g_W[idx] = (a0 + a1) + (a2 + a3);
    } else if (idx < NW + DPROJ) {
        int j = idx - NW;
        float acc = 0.f;
        #pragma unroll 4
        for (int d = 0; d < 128; d++)
            acc = fmaf(in_proj_w[j * 128 + d], mixer_b[d], acc);
        g_bias[j] = acc;
    } else if (idx < NW + DPROJ + DINNER) {
        int i = idx - NW - DPROJ;
        float acc = 0.f;
        #pragma unroll 4
        for (int d = 0; d < 128; d++)
            acc = fmaf(out_proj_w[d * DINNER + i], head_w[d], acc);
        g_v[i] = acc;
    }
}

// =====================================================================
// prep2: W (k<128) -> fp16 chunk tiles [jc][n(72)][k(128)]; pad Wcol/bias
// =====================================================================
__global__ void prep2_kernel() {
    int idx = blockIdx.x * blockDim.x + threadIdx.x;
    const int NH = NJC * TN * TK;            // 73728
    if (idx < NH) {
        int k = idx & 127;
        int t = idx >> 7;
        int n = t % TN;
        int jc = t / TN;
        int j = jc * TN + n;
        float val = (j < DPROJ) ? g_W[j * NCH + k] : 0.f;
        g_Wh[idx] = __float2half(val);
    } else if (idx < NH + 576) {
        int j = idx - NH;
        g_Wcol[j] = (j < DPROJ) ? g_W[j * NCH + 128] : 0.f;
    } else if (idx < NH + 1152) {
        int j = idx - NH - 576;
        g_biasP[j] = (j < DPROJ) ? g_bias[j] : 0.f;
    }
}

// =====================================================================
// gemm_mma: 2-pass fp16 split GEMM (A = xh + xl vs W fp16)
//   grid (2 tt, 8 jc, 512 b), 256 thr, 2 CTA/SM
// =====================================================================
__global__ void __launch_bounds__(256, 2) gemm_mma(const float* __restrict__ x) {
    extern __shared__ __align__(16) unsigned char sm[];
    const uint32_t sbase = smem_u32(sm);
    const int tid = threadIdx.x;
    const int wid = tid >> 5, lane = tid & 31;
    const int gid = lane >> 2, tig = lane & 3;
    const int tt = blockIdx.x, jc = blockIdx.y, b = blockIdx.z;
    const int t0 = tt * TM;

    // ---- B tile: fp16 W chunk (256 B/row -> pitch 272)
    {
        const unsigned char* src = (const unsigned char*)(g_Wh + (size_t)jc * (TN * TK));
        for (int i = tid; i < TN * 16; i += 256) {
            int n = i >> 4, q = i & 15;
            *(uint4*)(sm + SM_BH + n * PITCHB + q * 16) = *(const uint4*)(src + n * 256 + q * 16);
        }
    }
    // ---- A tile: x fp32 -> fp16 hi/lo pairs
    {
        const float* xb = x + (size_t)b * (NCH * NT);
        for (int i = tid; i < 64 * TM; i += 256) {
            int cp = i >> 7, m = i & (TM - 1);
            int t = t0 + m;
            int c0 = 2 * cp;
            float v0 = (t < NT) ? xb[(size_t)c0 * NT + t] : 0.f;
            float v1 = (t < NT) ? xb[(size_t)(c0 + 1) * NT + t] : 0.f;
            __half h0 = __float2half(v0), h1 = __float2half(v1);
            __half l0 = __float2half(v0 - __half2float(h0));
            __half l1 = __float2half(v1 - __half2float(h1));
            uint32_t off = (uint32_t)m * PITCHB + (uint32_t)cp * 4;
            *(__half2*)(sm + SM_AHI + off) = __half2{h0, h1};
            *(__half2*)(sm + SM_ALO + off) = __half2{l0, l1};
        }
    }
    // ---- epilogue constants
    if (tid < 128) {
        int t = t0 + tid;
        const float* xb = x + (size_t)b * (NCH * NT);
        *(float*)(sm + SM_X128 + tid * 4) = (t < NT) ? xb[(size_t)128 * NT + t] : 0.f;
        if (tid < TN) {
            *(float*)(sm + SM_W128 + tid * 4) = g_Wcol[jc * TN + tid];
            *(float*)(sm + SM_BIAS + tid * 4) = g_biasP[jc * TN + tid];
        }
    }
    __syncthreads();

    // ---- mainloop: 8 k-steps, B frags shared across hi/lo passes ----
    float acc[9][4];
    #pragma unroll
    for (int ni = 0; ni < 9; ni++)
        #pragma unroll
        for (int q = 0; q < 4; q++) acc[ni][q] = 0.f;

    const uint32_t aOff = (uint32_t)(wid * 16 + (lane & 15)) * PITCHB + (uint32_t)(lane >> 4) * 16;
    const uint32_t bOff = (uint32_t)(lane & 15) * PITCHB + (uint32_t)(lane >> 4) * 16;
    const uint32_t b2Off = (uint32_t)(64 + (lane & 7)) * PITCHB + (uint32_t)((lane >> 3) & 1) * 16;

    const uint32_t Ah = sbase + SM_AHI + aOff;
    const uint32_t Al = sbase + SM_ALO + aOff;
    const uint32_t Bb = sbase + SM_BH + bOff;
    const uint32_t Bb2 = sbase + SM_BH + b2Off;

    #pragma unroll
    for (int kk = 0; kk < NKK; kk++) {
        uint32_t ah[4], al[4];
        ldsm4(ah, Ah + kk * 32);
        ldsm4(al, Al + kk * 32);
        #pragma unroll
        for (int q = 0; q < 4; q++) {
            uint32_t bb[4];
            ldsm4(bb, Bb + (uint32_t)(q * 16) * PITCHB + kk * 32);
            uint32_t f0[2] = { bb[0], bb[2] };
            uint32_t f1[2] = { bb[1], bb[3] };
            mma16816(acc[2 * q],     ah, f0);
            mma16816(acc[2 * q],     al, f0);
            mma16816(acc[2 * q + 1], ah, f1);
            mma16816(acc[2 * q + 1], al, f1);
        }
        uint32_t b2[2];
        ldsm2(b2, Bb2 + kk * 32);
        mma16816(acc[8], ah, b2);
        mma16816(acc[8], al, b2);
    }

    // ---- stage accumulators to smem (reuse A region) ----
    __syncthreads();
    float* stage = (float*)sm;              // 128 x 76 fp32
    {
        int r = wid * 16 + gid;
        #pragma unroll
        for (int ni = 0; ni < 9; ni++) {
            int c = ni * 8 + 2 * tig;
            *(float2*)(stage + r * SPITCH + c) = make_float2(acc[ni][0], acc[ni][1]);
            *(float2*)(stage + (r + 8) * SPITCH + c) = make_float2(acc[ni][2], acc[ni][3]);
        }
    }
    __syncthreads();

    // ---- global store: + x128*W128 + bias, coalesced float4 ----
    const float* xs128 = (const float*)(sm + SM_X128);
    const float* sW = (const float*)(sm + SM_W128);
    const float* sBs = (const float*)(sm + SM_BIAS);
    for (int i = tid; i < TM * (TN / 4); i += 256) {
        int row = i / (TN / 4), q = i % (TN / 4);
        int t = t0 + row;
        int j = jc * TN + 4 * q;
        if (t < NT && j + 3 < DPROJ) {
            const float* sp = stage + row * SPITCH + 4 * q;
            float xk = xs128[row];
            float4 o;
            o.x = fmaf(xk, sW[4 * q + 0], sp[0] + sBs[4 * q + 0]);
            o.y = fmaf(xk, sW[4 * q + 1], sp[1] + sBs[4 * q + 1]);
            o.z = fmaf(xk, sW[4 * q + 2], sp[2] + sBs[4 * q + 2]);
            o.w = fmaf(xk, sW[4 * q + 3], sp[3] + sBs[4 * q + 3]);
            *(float4*)(g_zxbcdt + ((size_t)b * NT + t) * DPROJ + j) = o;
        }
    }
}

// =====================================================================
// scan: 160 threads, 2 channels/thread, deferred RMSNorm, 1 barrier/step
//   tid 0..143 : conv+silu for channels {2tid, 2tid+1}
//   tid 0..127 : SSM scan + gate for those channels
//   tid 128..135 / 136..143 : B / C producers
//   tid 144..147: dt producer (head tid-144)
// =====================================================================
__global__ void __launch_bounds__(160, 4)
scan_kernel(const float* __restrict__ conv_w, const float* __restrict__ conv_b,
            const float* __restrict__ dt_bias, const float* __restrict__ A_log,
            const float* __restrict__ Dp, const float* __restrict__ norm_w,
            const float* __restrict__ head_b, float* __restrict__ out) {
    const int b = blockIdx.x;
    const int tid = threadIdx.x;
    const int lane = tid & 31, wid = tid >> 5;
    const int c0 = 2 * tid;
    const int h = tid >> 5;                  // head for scan threads (tid<128)

    __shared__ __align__(8) float2 sB2[2][DSTATE];   // duplicated pairs (v,v)
    __shared__ __align__(8) float2 sC2[2][DSTATE];
    __shared__ float sdA[2][NHEADS], sdt[2][NHEADS];
    __shared__ __align__(8) float2 sPS[NT][4];       // per-(t,warp) partial (ss, p)
    __shared__ float sfin[5];

    const bool isConv = (tid < 144);
    const bool isScan = (tid < 128);
    const bool isDt   = (tid >= 144 && tid < 148);

    // per-thread conv params (2 channels, packed)
    ull wk2[4]; ull cb2 = 0ULL;
    if (isConv) {
        #pragma unroll
        for (int k = 0; k < 4; k++)
            wk2[k] = pack2(conv_w[c0 * 4 + k], conv_w[(c0 + 1) * 4 + k]);
        cb2 = pack2(conv_b[c0], conv_b[c0 + 1]);
    } else {
        wk2[0] = wk2[1] = wk2[2] = wk2[3] = 0ULL;
    }
    ull h1 = 0ULL, h2 = 0ULL, h3 = 0ULL;   // conv history (2 ch packed)

    ull nw2 = 0ULL; float Dh = 0.f;
    if (isScan) {
        nw2 = pack2(norm_w[c0] * g_v[c0], norm_w[c0 + 1] * g_v[c0 + 1]);
        Dh = Dp[h];
    }
    float dtb = 0.f, Aneg = 0.f;
    if (isDt) { dtb = dt_bias[tid - 144]; Aneg = -expf(A_log[tid - 144]); }

    ull s2[DSTATE];
    #pragma unroll
    for (int n = 0; n < DSTATE; n++) s2[n] = 0ULL;

    const float* row = g_zxbcdt + (size_t)b * NT * DPROJ;

    // prefetch t=0
    ull raw2 = 0ULL; float2 z2 = make_float2(0.f, 0.f); float dtr = 0.f;
    if (isConv) raw2 = *(const ull*)(row + DINNER + c0);
    if (isScan) z2 = *(const float2*)(row + c0);
    if (isDt)   dtr = row[DPROJ - NHEADS + (tid - 144)];

    for (int t = 0; t < NT; t++) {
        const int buf = t & 1;

        // conv (packed) + silu per lane
        float cs0 = 0.f, cs1 = 0.f;
        if (isConv) {
            ull cv2 = ffma2(wk2[3], raw2,
                      ffma2(wk2[2], h1,
                      ffma2(wk2[1], h2,
                      ffma2(wk2[0], h3, cb2))));
            h3 = h2; h2 = h1; h1 = raw2;
            float2 cv = unpk2(cv2);
            cs0 = __fdividef(cv.x, 1.f + __expf(-cv.x));
            cs1 = __fdividef(cv.y, 1.f + __expf(-cv.y));
            if (tid >= 128) {
                if (tid < 136) {
                    sB2[buf][2 * (tid - 128)]     = make_float2(cs0, cs0);
                    sB2[buf][2 * (tid - 128) + 1] = make_float2(cs1, cs1);
                } else {
                    sC2[buf][2 * (tid - 136)]     = make_float2(cs0, cs0);
                    sC2[buf][2 * (tid - 136) + 1] = make_float2(cs1, cs1);
                }
            }
        }
        if (isDt) {
            float rv = dtr + dtb;
            float dtv = (rv > 15.f) ? rv : __logf(1.f + __expf(rv));
            sdt[buf][tid - 144] = dtv;
            sdA[buf][tid - 144] = __expf(dtv * Aneg);
        }

        // prefetch t+1
        ull nraw2 = 0ULL; float2 nz2 = make_float2(0.f, 0.f); float ndtr = 0.f;
        if (t + 1 < NT) {
            const float* rn = row + (size_t)(t + 1) * DPROJ;
            if (isConv) nraw2 = *(const ull*)(rn + DINNER + c0);
            if (isScan) nz2 = *(const float2*)(rn + c0);
            if (isDt)   ndtr = rn[DPROJ - NHEADS + (tid - 144)];
        }
        __syncthreads();

        if (isScan) {
            float dtv = sdt[buf][h];
            ull dA2 = dup2(sdA[buf][h]);
            ull dx2 = pack2(dtv * cs0, dtv * cs1);
            ull y2 = 0ULL;
            #pragma unroll
            for (int n = 0; n < DSTATE; n++) {
                s2[n] = ffma2(s2[n], dA2, fmul2(dx2, *(const ull*)&sB2[buf][n]));
                y2 = ffma2(s2[n], *(const ull*)&sC2[buf][n], y2);
            }
            float2 yy = unpk2(y2);
            float y0 = fmaf(Dh, cs0, yy.x);
            float y1 = fmaf(Dh, cs1, yy.y);
            float g0 = y0 * __fdividef(z2.x, 1.f + __expf(-z2.x));
            float g1 = y1 * __fdividef(z2.y, 1.f + __expf(-z2.y));

            float ss = fmaf(g0, g0, g1 * g1);
            float p  = fmaf(g0, __uint_as_float((uint32_t)(nw2 & 0xffffffffu)),
                            g1 * __uint_as_float((uint32_t)(nw2 >> 32)));
            #pragma unroll
            for (int o = 16; o > 0; o >>= 1) {
                ss += __shfl_xor_sync(0xffffffffu, ss, o);
                p  += __shfl_xor_sync(0xffffffffu, p, o);
            }
            if (lane == 0) sPS[t][wid] = make_float2(ss, p);
        }

        raw2 = nraw2; z2 = nz2; dtr = ndtr;
    }

    // final phase: apply deferred rsqrt per timestep, accumulate
    __syncthreads();
    float facc = 0.f;
    for (int t = tid; t < NT; t += 160) {
        float2 a = sPS[t][0], b2 = sPS[t][1], c = sPS[t][2], d = sPS[t][3];
        float SS = (a.x + b2.x) + (c.x + d.x);
        float P  = (a.y + b2.y) + (c.y + d.y);
        facc = fmaf(P, rsqrtf(SS * (1.f / 256.f) + EPSV), facc);
    }
    #pragma unroll
    for (int o = 16; o > 0; o >>= 1) facc += __shfl_xor_sync(0xffffffffu, facc, o);
    if (lane == 0) sfin[wid] = facc;
    __syncthreads();
    if (tid == 0) {
        float tot = (sfin[0] + sfin[1]) + (sfin[2] + sfin[3]) + sfin[4];
        out[b] = tot * (1.f / (float)NT) + head_b[0];
    }
}

// =====================================================================
// launch
// =====================================================================
extern "C" void kernel_launch(void* const* d_in, const int* in_sizes, int n_in,
                              void* d_out, int out_size) {
    const float* x          = (const float*)d_in[0];
    const float* mixer_w    = (const float*)d_in[1];
    const float* mixer_b    = (const float*)d_in[2];
    const float* in_proj_w  = (const float*)d_in[3];
    const float* conv_w     = (const float*)d_in[4];
    const float* conv_b     = (const float*)d_in[5];
    const float* dt_bias    = (const float*)d_in[6];
    const float* A_log      = (const float*)d_in[7];
    const float* Dvec       = (const float*)d_in[8];
    const float* norm_w     = (const float*)d_in[9];
    const float* out_proj_w = (const float*)d_in[10];
    const float* head_w     = (const float*)d_in[11];
    const float* head_b     = (const float*)d_in[12];
    float* out = (float*)d_out;

    {
        int total = DPROJ * NCH + DPROJ + DINNER;
        prep1_kernel<<<(total + 255) / 256, 256>>>(in_proj_w, mixer_w, mixer_b,
                                                   out_proj_w, head_w);
    }
    {
        int total = NJC * TN * TK + 1152;
        prep2_kernel<<<(total + 255) / 256, 256>>>();
    }
    {
        cudaFuncSetAttribute(gemm_mma,
                             cudaFuncAttributeMaxDynamicSharedMemorySize, SMEM_SZ);
        dim3 grid(2, NJC, BSZ);
        gemm_mma<<<grid, 256, SMEM_SZ>>>(x);
    }
    scan_kernel<<<BSZ, 160>>>(conv_w, conv_b, dt_bias, A_log, Dvec,
                              norm_w, head_b, out);
}